// round 5
// baseline (speedup 1.0000x reference)
#include <cuda_runtime.h>
#include <cstdint>

// 2D acoustic FDTD, 500 steps, 8 shots, 256x256, 128 recs/shot.
// One persistent kernel; shot = 8-CTA cluster; fields in SMEM.
// 1024 threads/CTA. Neighbor sync via monotonic DSMEM progress flags
// (st.release.cluster / ld.acquire spin) -- no cluster.sync in the loop.

#define DT 0.001f
#define DX 10.0f

constexpr int NT   = 500;
constexpr int NS   = 8;
constexpr int NZ   = 256;
constexpr int NXC  = 256;
constexpr int NREC = 128;

constexpr int CSZ  = 8;
constexpr int ROWS = NZ / CSZ;          // 32
constexpr int NTHREADS = 1024;
constexpr int COL4 = NXC / 4;           // 64
constexpr int RG   = NTHREADS / COL4;   // 16 row-groups
constexpr int RPT  = ROWS / RG;         // 2 rows per thread

constexpr int BUF_ELEMS = ROWS * NXC;   // 8192
constexpr size_t SMEM_BYTES = (size_t)(2 * BUF_ELEMS + 512) * sizeof(float);

// ---------------------------------------------------------------- PTX helpers
__device__ __forceinline__ uint32_t cvta_smem(const void* p) {
    return (uint32_t)__cvta_generic_to_shared(p);
}
__device__ __forceinline__ uint32_t mapa_cluster(uint32_t laddr, uint32_t rank) {
    uint32_t r;
    asm("mapa.shared::cluster.u32 %0, %1, %2;" : "=r"(r) : "r"(laddr), "r"(rank));
    return r;
}
__device__ __forceinline__ float4 ld_dsmem_v4(uint32_t addr) {
    float4 v;
    asm volatile("ld.shared::cluster.v4.f32 {%0,%1,%2,%3}, [%4];"
                 : "=f"(v.x), "=f"(v.y), "=f"(v.z), "=f"(v.w) : "r"(addr));
    return v;
}
__device__ __forceinline__ void cluster_sync_() {
    asm volatile("barrier.cluster.arrive.aligned;" ::: "memory");
    asm volatile("barrier.cluster.wait.aligned;" ::: "memory");
}
__device__ __forceinline__ uint32_t cluster_rank_() {
    uint32_t r;
    asm("mov.u32 %0, %%cluster_ctarank;" : "=r"(r));
    return r;
}
// monotonic progress flags: remote release-store, local acquire-load spin
__device__ __forceinline__ void st_flag_remote(uint32_t addr, uint32_t val) {
    asm volatile("st.release.cluster.shared::cluster.u32 [%0], %1;"
                 :: "r"(addr), "r"(val) : "memory");
}
__device__ __forceinline__ uint32_t ld_flag_acq(uint32_t addr) {
    uint32_t v;
    asm volatile("ld.acquire.cluster.shared::cta.u32 %0, [%1];"
                 : "=r"(v) : "r"(addr) : "memory");
    return v;
}

// ---------------------------------------------------------------- kernel
__global__ void __cluster_dims__(CSZ, 1, 1) __launch_bounds__(NTHREADS, 1)
wave_kernel(const float* __restrict__ x,     // (NT, NS)
            const float* __restrict__ vp,    // (NZ, NXC)
            const int*   __restrict__ src,   // (NS, 2)
            const int*   __restrict__ rec,   // (NS, NREC, 2)
            float*       __restrict__ out)   // (NT, NS, NREC)
{
    extern __shared__ float sm[];
    float* buf0 = sm;
    float* buf1 = sm + BUF_ELEMS;
    float* xs   = sm + 2 * BUF_ELEMS;

    __shared__ unsigned int flag_n, flag_s;   // progress of north/south neighbor
    __shared__ int rcnt;
    __shared__ int2 rlist[NREC];

    const int tid  = threadIdx.x;
    const uint32_t rank = cluster_rank_();
    const int shot = blockIdx.x / CSZ;

    const int col4 = tid & (COL4 - 1);
    const int rg   = tid >> 6;           // 0..15
    const int lr0  = rg * RPT;           // 2*rg
    const int xcol = col4 * 4;
    const bool has_n = (rank > 0);
    const bool has_s = (rank < CSZ - 1);

    // --- init ----------------------------------------------------------------
    for (int i = tid; i < BUF_ELEMS; i += NTHREADS) { buf0[i] = 0.f; buf1[i] = 0.f; }
    for (int i = tid; i < NT; i += NTHREADS) xs[i] = x[i * NS + shot];
    if (tid == 0) { rcnt = 0; flag_n = 0; flag_s = 0; }
    __syncthreads();

    // claim receivers owned by this CTA (rz in [rank*ROWS, (rank+1)*ROWS))
    if (tid < NREC) {
        const int gi = shot * NREC + tid;
        const int rz = rec[gi * 2 + 0];
        const int rx = rec[gi * 2 + 1];
        if ((uint32_t)(rz >> 5) == rank) {
            int s = atomicAdd(&rcnt, 1);
            rlist[s] = make_int2((rz & 31) * NXC + rx, shot * NREC + tid);
        }
    }

    // c2 in registers
    float4 c2r[RPT];
    const float sc = DT / DX;
#pragma unroll
    for (int j = 0; j < RPT; j++) {
        const int g = (int)rank * ROWS + lr0 + j;
        float4 v = *(const float4*)(vp + g * NXC + xcol);
        float a = v.x * sc, b = v.y * sc, c = v.z * sc, d = v.w * sc;
        c2r[j] = make_float4(a * a, b * b, c * c, d * d);
    }

    // prev in registers (zero at t=0)
    float4 pr[RPT];
#pragma unroll
    for (int j = 0; j < RPT; j++) pr[j] = make_float4(0.f, 0.f, 0.f, 0.f);

    // source ownership
    const int sz = src[shot * 2 + 0];
    const int sx = src[shot * 2 + 1];
    const int sj = sz - ((int)rank * ROWS + lr0);
    const bool shere = (sj >= 0 && sj < RPT && sx >= xcol && sx < xcol + 4);
    const int scomp = sx - xcol;

    // DSMEM halo addresses (both parities)
    const uint32_t sa0 = cvta_smem(buf0);
    const uint32_t sa1 = cvta_smem(buf1);
    uint32_t nh_addr[2] = {0, 0}, sh_addr[2] = {0, 0};
    if (rg == 0 && has_n) {
        const uint32_t off = (uint32_t)((ROWS - 1) * NXC + xcol) * 4u;
        nh_addr[0] = mapa_cluster(sa0 + off, rank - 1);
        nh_addr[1] = mapa_cluster(sa1 + off, rank - 1);
    }
    if (rg == RG - 1 && has_s) {
        const uint32_t off = (uint32_t)(xcol) * 4u;
        sh_addr[0] = mapa_cluster(sa0 + off, rank + 1);
        sh_addr[1] = mapa_cluster(sa1 + off, rank + 1);
    }

    // remote flag addresses: I am the south neighbor of rank-1 (its flag_s),
    // and the north neighbor of rank+1 (its flag_n).
    uint32_t rf_n = 0, rf_s = 0;
    if (tid == 0) {
        if (has_n) rf_n = mapa_cluster(cvta_smem(&flag_s), rank - 1);
        if (has_s) rf_s = mapa_cluster(cvta_smem(&flag_n), rank + 1);
    }
    const uint32_t fa_n = cvta_smem(&flag_n);
    const uint32_t fa_s = cvta_smem(&flag_s);

    __syncthreads();
    const bool samp = (tid < rcnt);
    int roff = 0;
    float* outp = out;
    if (samp) {
        int2 e = rlist[tid];
        roff = e.x;
        outp = out + e.y;
    }

    cluster_sync_();  // zeroed buffers + zeroed flags visible cluster-wide

    // --- main time loop ------------------------------------------------------
    int p = 0;
    for (int t = 0; t < NT; t++) {
        const float* cur = p ? buf1 : buf0;
        float*       nxt = p ? buf0 : buf1;
        const int toff = (t + 2 < NT - 1) ? t + 2 : NT - 1;
        const float amp = xs[t] + xs[toff];

        // boundary row-groups wait until neighbor finished step t-1.
        // Monotonic counter: no parity aliasing at any drift.
        if (t > 0) {
            if (rg == 0 && has_n) {
                while (ld_flag_acq(fa_n) < (uint32_t)t) { }
            }
            if (rg == RG - 1 && has_s) {
                while (ld_flag_acq(fa_s) < (uint32_t)t) { }
            }
        }

        // north value for first row of strip
        float4 cN;
        if (rg == 0) {
            cN = has_n ? ld_dsmem_v4(nh_addr[p]) : make_float4(0.f, 0.f, 0.f, 0.f);
        } else {
            cN = *(const float4*)(cur + (lr0 - 1) * NXC + xcol);
        }
        float4 cC = *(const float4*)(cur + lr0 * NXC + xcol);

#pragma unroll
        for (int j = 0; j < RPT; j++) {
            const int lr = lr0 + j;
            float4 cS;
            if (j == RPT - 1 && rg == RG - 1) {   // lr == ROWS-1
                cS = has_s ? ld_dsmem_v4(sh_addr[p])
                           : make_float4(0.f, 0.f, 0.f, 0.f);
            } else {
                cS = *(const float4*)(cur + (lr + 1) * NXC + xcol);
            }
            const float lft = (xcol > 0)       ? cur[lr * NXC + xcol - 1] : 0.f;
            const float rgt = (xcol + 4 < NXC) ? cur[lr * NXC + xcol + 4] : 0.f;

            float4 lap;
            lap.x = cN.x + cS.x + lft  + cC.y - 4.f * cC.x;
            lap.y = cN.y + cS.y + cC.x + cC.z - 4.f * cC.y;
            lap.z = cN.z + cS.z + cC.y + cC.w - 4.f * cC.z;
            lap.w = cN.w + cS.w + cC.z + rgt  - 4.f * cC.w;

            float4 nv;
            nv.x = 2.f * cC.x - pr[j].x + c2r[j].x * lap.x;
            nv.y = 2.f * cC.y - pr[j].y + c2r[j].y * lap.y;
            nv.z = 2.f * cC.z - pr[j].z + c2r[j].z * lap.z;
            nv.w = 2.f * cC.w - pr[j].w + c2r[j].w * lap.w;

            if (shere && j == sj) {
                if      (scomp == 0) nv.x += amp;
                else if (scomp == 1) nv.y += amp;
                else if (scomp == 2) nv.z += amp;
                else                 nv.w += amp;
            }

            *(float4*)(nxt + lr * NXC + xcol) = nv;
            pr[j] = cC;
            cN = cC;
            cC = cS;
        }

        __syncthreads();   // all nxt stores visible CTA-wide

        // publish step t to neighbors (release makes all CTA writes visible:
        // they happen-before the syncthreads, which happens-before this store)
        if (tid == 0) {
            const uint32_t v = (uint32_t)(t + 1);
            if (has_n) st_flag_remote(rf_n, v);
            if (has_s) st_flag_remote(rf_s, v);
        }

        // owner-local receiver sampling from the freshly written buffer
        if (samp) {
            *outp = nxt[roff];
            outp += NS * NREC;
        }

        p ^= 1;
    }

    cluster_sync_();  // keep cluster smem alive until all CTAs are done
}

// ---------------------------------------------------------------- launch
extern "C" void kernel_launch(void* const* d_in, const int* in_sizes, int n_in,
                              void* d_out, int out_size)
{
    const float* x   = (const float*)d_in[0];
    const float* vp  = (const float*)d_in[1];
    const int*   src = (const int*)d_in[2];
    const int*   rec = (const int*)d_in[3];
    float*       out = (float*)d_out;

    cudaFuncSetAttribute((const void*)wave_kernel,
                         cudaFuncAttributeMaxDynamicSharedMemorySize,
                         (int)SMEM_BYTES);

    wave_kernel<<<NS * CSZ, NTHREADS, SMEM_BYTES>>>(x, vp, src, rec, out);
}